// round 15
// baseline (speedup 1.0000x reference)
#include <cuda_runtime.h>
#include <cuda_fp16.h>
#include <math.h>
#include <stdint.h>

// Problem constants
#define BN 8
#define CC 256
#define CI 512        // 2C
#define HH 64
#define WW 64
#define KK 4
#define HW (HH*WW)          // 4096
#define CHW (CC*HW)         // 1048576
#define NOUT (BN*CHW)       // 8388608 per tensor
#define KTOT 4608           // CI*9
#define WSCALE 1024.0f
#define INV_WSCALE (1.0f/1024.0f)

// ---------------- scratch (device globals; no allocation allowed) ----------
__device__ __half g_Fm[NOUT];                       // conv+leaky output (fp16 NCHW)
__device__ __half g_Xh[BN*HH*WW*CI];                // NHWC fp16 image
__device__ __half g_Wh[CC*KTOT];                    // [co][tap*512+ci] (w*1024) fp16
__device__ float g_U1[BN*CC*KK];
__device__ float g_U2[BN*WW*KK];
__device__ float g_U3[BN*HH*KK];
__device__ float g_Mc[3*KK*3];
__device__ float g_spatial[BN*HW];
__device__ float g_spec[BN*CC];
__device__ float g_ga[BN*CC];
__device__ float g_gm[BN*CC];
__device__ float g_V1[BN*CC*KK];
// mode pooling partials: [b][n][c] layout (n = h or w)
__device__ float g_prS[BN*64*256];
__device__ float g_prM[BN*64*256];
__device__ float g_pcS[BN*64*256];
__device__ float g_pcM[BN*64*256];

// ================= PTX helpers ==============================================
__device__ __forceinline__ uint32_t smem_u32(const void* p) {
    uint32_t a;
    asm("{ .reg .u64 t; cvta.to.shared.u64 t, %1; cvt.u32.u64 %0, t; }" : "=r"(a) : "l"(p));
    return a;
}
__device__ __forceinline__ void cp_async16(uint32_t dst, const void* src, uint32_t srcSize) {
    asm volatile("cp.async.ca.shared.global [%0], [%1], 16, %2;"
                 :: "r"(dst), "l"(src), "r"(srcSize) : "memory");
}
#define CP_COMMIT() asm volatile("cp.async.commit_group;" ::: "memory")
#define CP_WAIT(n)  asm volatile("cp.async.wait_group %0;" :: "n"(n) : "memory")

__device__ __forceinline__ void ldsm4(uint32_t addr, uint32_t r[4]) {
    asm volatile("ldmatrix.sync.aligned.m8n8.x4.shared.b16 {%0,%1,%2,%3}, [%4];"
                 : "=r"(r[0]), "=r"(r[1]), "=r"(r[2]), "=r"(r[3]) : "r"(addr));
}
__device__ __forceinline__ void mma16816(float c[4], const uint32_t a[4], const uint32_t b[2]) {
    asm volatile("mma.sync.aligned.m16n8k16.row.col.f32.f16.f16.f32 "
                 "{%0,%1,%2,%3}, {%4,%5,%6,%7}, {%8,%9}, {%0,%1,%2,%3};"
                 : "+f"(c[0]), "+f"(c[1]), "+f"(c[2]), "+f"(c[3])
                 : "r"(a[0]), "r"(a[1]), "r"(a[2]), "r"(a[3]), "r"(b[0]), "r"(b[1]));
}
#define SWZ(x) ((x) ^ (((x) >> 3) & 0x70))
__device__ __forceinline__ float sigm(float x) { return 1.f / (1.f + expf(-x)); }

// ---------------- prep: weights*1024 -> fp16; block(0,0) also folds adapters -
__global__ __launch_bounds__(256) void prep_w_kernel(
    const float* __restrict__ W3,
    const float* __restrict__ Wu, const float* __restrict__ bu,
    const float* __restrict__ Wa1, const float* __restrict__ ba1,
    const float* __restrict__ Wa2, const float* __restrict__ ba2,
    const float* __restrict__ Wa3, const float* __restrict__ ba3) {
    int co = blockIdx.y;
    int r = blockIdx.x * 256 + threadIdx.x;   // 0..4607
    int tap = r >> 9, ci = r & 511;
    float v = W3[((size_t)co * CI + ci) * 9 + tap] * WSCALE;
    g_Wh[(size_t)co * KTOT + r] = __float2half_rn(v);

    if (blockIdx.x == 0 && blockIdx.y == 0 && threadIdx.x < 12) {
        int t = threadIdx.x;
        int m = t >> 2, k = t & 3;
        const float* Wa = (m == 0) ? Wa1 : ((m == 1) ? Wa2 : Wa3);
        const float* ba = (m == 0) ? ba1 : ((m == 1) ? ba2 : ba3);
        float m0 = 0.f, m1 = 0.f, cc = 0.f;
        for (int o = 0; o < CC; o++) {
            float wu = Wu[k * CC + o];
            m0 += wu * Wa[o * 2 + 0];
            m1 += wu * Wa[o * 2 + 1];
            cc += wu * ba[o];
        }
        g_Mc[(m * KK + k) * 3 + 0] = m0;
        g_Mc[(m * KK + k) * 3 + 1] = m1;
        g_Mc[(m * KK + k) * 3 + 2] = cc + bu[k];
    }
}

// ---------------- prep: inputs NCHW fp32 -> NHWC fp16 -----------------------
__global__ __launch_bounds__(256) void prep_x_kernel(const float* __restrict__ frm,
                                                     const float* __restrict__ other) {
    __shared__ float S[64][65];
    int by = blockIdx.x;           // b*64 + y
    int b = by >> 6, y = by & 63;
    int cc = blockIdx.y;           // ci chunk of 64
    int tid = threadIdx.x;
#pragma unroll
    for (int i = 0; i < 16; i++) {
        int idx = i * 256 + tid;
        int ciL = idx >> 6, x = idx & 63;
        int ciX = cc * 64 + ciL;
        const float* src = (ciX < CC) ? frm : other;
        int cs = ciX & 255;
        S[ciL][x] = src[((size_t)(b * CC + cs) * HH + y) * WW + x];
    }
    __syncthreads();
#pragma unroll
    for (int i = 0; i < 16; i++) {
        int idx = i * 256 + tid;
        int x = idx >> 6, ciL = idx & 63;
        size_t d = ((size_t)(b * 64 + y) * 64 + x) * CI + cc * 64 + ciL;
        g_Xh[d] = __float2half_rn(S[ciL][x]);
    }
}

// ---------------- conv via mma.sync fp16 implicit GEMM ----------------------
#define STAGE_B 98304
#define A_SUB   32768
#define B_OFF   65536
#define B_SUB   16384
#define DSMEM_BYTES (2*STAGE_B + 1024)

__device__ __forceinline__ void stage_load64(uint32_t aBase, uint32_t bBase,
                                             int m0, int co0, int oc, int tid) {
    const int tap = oc >> 3, cic = oc & 7;
    const int ky = tap / 3 - 1, kx = tap % 3 - 1;
    const int ci0 = cic * 64;
#pragma unroll
    for (int it = 0; it < 4; it++) {
        int idx = it * 512 + tid;
        int r = idx >> 3, q = idx & 7;
        int p = m0 + r;
        int b = p >> 12;
        int ys = ((p >> 6) & 63) + ky, xs = (p & 63) + kx;
        bool ok = ((unsigned)ys < 64u) && ((unsigned)xs < 64u);
        const void* src = ok
            ? (const void*)(g_Xh + (((size_t)(b * 64 + ys) * 64 + xs) * CI + ci0 + q * 8))
            : (const void*)g_Xh;
        uint32_t full = (uint32_t)(r * 128 + q * 16);
        cp_async16(aBase + SWZ(full), src, ok ? 16u : 0u);
    }
#pragma unroll
    for (int it = 0; it < 2; it++) {
        int idx = it * 512 + tid;
        int r = idx >> 3, q = idx & 7;
        const void* src = g_Wh + ((size_t)(co0 + r) * KTOT + oc * 64 + q * 8);
        uint32_t full = (uint32_t)(r * 128 + q * 16);
        cp_async16(bBase + SWZ(full), src, 16u);
    }
}

__device__ __forceinline__ void stage_load128(uint32_t smStage, int m0, int co0,
                                              int c36, int tid) {
    stage_load64(smStage,         smStage + B_OFF,         m0, co0, 2 * c36,     tid);
    stage_load64(smStage + A_SUB, smStage + B_OFF + B_SUB, m0, co0, 2 * c36 + 1, tid);
}

__global__ __launch_bounds__(512, 1)
void conv_mma_kernel(const float* __restrict__ b3) {
    extern __shared__ __align__(128) char dynsm_raw[];
    const uint32_t smBase = (smem_u32(dynsm_raw) + 1023) & ~1023u;

    const int tid = threadIdx.x;
    const int lane = tid & 31;
    const int w = tid >> 5;
    const int wm = w & 3, wn = w >> 2;
    const int m0 = (int)blockIdx.x * 256;
    const int co0 = (int)blockIdx.y * 128;

    float acc[4][4][4];
#pragma unroll
    for (int mf = 0; mf < 4; mf++)
#pragma unroll
        for (int nf = 0; nf < 4; nf++)
#pragma unroll
            for (int j = 0; j < 4; j++) acc[mf][nf][j] = 0.f;

    const uint32_t aRowOff = (uint32_t)((wm * 64 + (lane & 15)) * 128);
    const uint32_t aColB   = (uint32_t)((lane >> 4) * 16);
    const uint32_t bRowOff = (uint32_t)((wn * 32 + (lane & 7) + ((lane >> 4) << 3)) * 128);
    const uint32_t bColB   = (uint32_t)(((lane >> 3) & 1) * 16);

    stage_load128(smBase, m0, co0, 0, tid);
    CP_COMMIT();

    for (int c = 0; c < 36; c++) {
        CP_WAIT(0);
        __syncthreads();

        if (c + 1 < 36) {
            stage_load128(smBase + (uint32_t)((c + 1) & 1) * STAGE_B, m0, co0, c + 1, tid);
            CP_COMMIT();
        }

        const uint32_t st = smBase + (uint32_t)(c & 1) * STAGE_B;
#pragma unroll
        for (int sub = 0; sub < 2; sub++) {
            const uint32_t aSt = st + (uint32_t)sub * A_SUB;
            const uint32_t bSt = st + B_OFF + (uint32_t)sub * B_SUB;
#pragma unroll
            for (int k16 = 0; k16 < 4; k16++) {
                const uint32_t kb = (uint32_t)(k16 * 32);
                uint32_t a[4][4], bb[4][2];
#pragma unroll
                for (int mf = 0; mf < 4; mf++) {
                    uint32_t aAddr = aSt + SWZ(aRowOff + (uint32_t)(mf * 2048) + aColB + kb);
                    ldsm4(aAddr, a[mf]);
                }
                {
                    uint32_t bAddr = bSt + SWZ(bRowOff + bColB + kb);
                    uint32_t rh[4];
                    ldsm4(bAddr, rh);
                    bb[0][0] = rh[0]; bb[0][1] = rh[1];
                    bb[1][0] = rh[2]; bb[1][1] = rh[3];
                    uint32_t bAddr2 = bSt + SWZ(bRowOff + 2048 + bColB + kb);
                    ldsm4(bAddr2, rh);
                    bb[2][0] = rh[0]; bb[2][1] = rh[1];
                    bb[3][0] = rh[2]; bb[3][1] = rh[3];
                }
#pragma unroll
                for (int mf = 0; mf < 4; mf++)
#pragma unroll
                    for (int nf = 0; nf < 4; nf++) mma16816(acc[mf][nf], a[mf], bb[nf]);
            }
        }
    }

    // epilogue: unscale + bias + leaky relu -> g_Fm (fp16 NCHW)
    const int rr = wm * 64 + (lane >> 2);
    const int ccb = co0 + wn * 32 + (lane & 3) * 2;
#pragma unroll
    for (int mf = 0; mf < 4; mf++) {
        int p = m0 + rr + mf * 16;
        int b = p >> 12;
        int pix = p & 4095;
#pragma unroll
        for (int nf = 0; nf < 4; nf++) {
            int co = ccb + nf * 8;
            float bi0 = __ldg(&b3[co]), bi1 = __ldg(&b3[co + 1]);
            float v0 = acc[mf][nf][0] * INV_WSCALE + bi0;
            float v1 = acc[mf][nf][1] * INV_WSCALE + bi1;
            float v2 = acc[mf][nf][2] * INV_WSCALE + bi0;
            float v3 = acc[mf][nf][3] * INV_WSCALE + bi1;
            v0 = (v0 > 0.f) ? v0 : 0.01f * v0;
            v1 = (v1 > 0.f) ? v1 : 0.01f * v1;
            v2 = (v2 > 0.f) ? v2 : 0.01f * v2;
            v3 = (v3 > 0.f) ? v3 : 0.01f * v3;
            size_t base0 = ((size_t)(b * CC + co) << 12) + pix;
            size_t base1 = ((size_t)(b * CC + co + 1) << 12) + pix;
            g_Fm[base0] = __float2half_rn(v0);
            g_Fm[base1] = __float2half_rn(v1);
            g_Fm[base0 + 8] = __float2half_rn(v2);
            g_Fm[base1 + 8] = __float2half_rn(v3);
        }
    }
}

// ---------------- modes pass1: 2 channels/block smem-plane pooling ----------
__global__ __launch_bounds__(256) void modes_pass1_kernel() {
    const int g2 = blockIdx.x;            // b*128 + cpair
    const int b = g2 >> 7, c0 = (g2 & 127) * 2;
    const int tid = threadIdx.x;

    __shared__ float S[2][64][65];
    __shared__ float rPS[2][4][64], rPM[2][4][64];
    __shared__ float cPS[2][4][64], cPM[2][4][64];
    __shared__ float tS[2][64], tM[2][64];

    // load 2 fp16 planes: 1024 uint4 / 256 thr = 4 each
    const uint4* p = (const uint4*)(g_Fm + (((size_t)(b * CC + c0)) << 12));
#pragma unroll
    for (int i = 0; i < 4; i++) {
        int idx = i * 256 + tid;          // 0..1023 ; plane = idx>>9
        uint4 v = p[idx];
        int pl = idx >> 9, rem = idx & 511;
        int r = rem >> 3, c8 = (rem & 7) * 8;
        float2 f0 = __half22float2(*(__half2*)&v.x);
        float2 f1 = __half22float2(*(__half2*)&v.y);
        float2 f2 = __half22float2(*(__half2*)&v.z);
        float2 f3 = __half22float2(*(__half2*)&v.w);
        S[pl][r][c8 + 0] = f0.x; S[pl][r][c8 + 1] = f0.y;
        S[pl][r][c8 + 2] = f1.x; S[pl][r][c8 + 3] = f1.y;
        S[pl][r][c8 + 4] = f2.x; S[pl][r][c8 + 5] = f2.y;
        S[pl][r][c8 + 6] = f3.x; S[pl][r][c8 + 7] = f3.y;
    }
    __syncthreads();

#pragma unroll
    for (int pl = 0; pl < 2; pl++) {
        {
            int r = tid & 63, sg = tid >> 6;
            const float* row = &S[pl][r][sg * 16];
            float s = 0.f, m = -3.4e38f;
#pragma unroll
            for (int j = 0; j < 16; j++) { float v = row[j]; s += v; m = fmaxf(m, v); }
            rPS[pl][sg][r] = s; rPM[pl][sg][r] = m;
        }
        {
            int col = tid & 63, sg = tid >> 6;
            float s = 0.f, m = -3.4e38f;
#pragma unroll
            for (int j = 0; j < 16; j++) { float v = S[pl][sg * 16 + j][col]; s += v; m = fmaxf(m, v); }
            cPS[pl][sg][col] = s; cPM[pl][sg][col] = m;
        }
    }
    __syncthreads();

#pragma unroll
    for (int pl = 0; pl < 2; pl++) {
        int c = c0 + pl;
        if (tid < 64) {
            float s = rPS[pl][0][tid] + rPS[pl][1][tid] + rPS[pl][2][tid] + rPS[pl][3][tid];
            float m = fmaxf(fmaxf(rPM[pl][0][tid], rPM[pl][1][tid]),
                            fmaxf(rPM[pl][2][tid], rPM[pl][3][tid]));
            g_prS[(b * 64 + tid) * 256 + c] = s;
            g_prM[(b * 64 + tid) * 256 + c] = m;
            tS[pl][tid] = s; tM[pl][tid] = m;
        } else if (tid < 128) {
            int wq = tid - 64;
            float s = cPS[pl][0][wq] + cPS[pl][1][wq] + cPS[pl][2][wq] + cPS[pl][3][wq];
            float m = fmaxf(fmaxf(cPM[pl][0][wq], cPM[pl][1][wq]),
                            fmaxf(cPM[pl][2][wq], cPM[pl][3][wq]));
            g_pcS[(b * 64 + wq) * 256 + c] = s;
            g_pcM[(b * 64 + wq) * 256 + c] = m;
        }
    }
    __syncthreads();

    if (tid < 64) {                       // warp 0 -> plane 0, warp 1 -> plane 1
        int pl = tid >> 5, lane = tid & 31;
        float s = tS[pl][lane] + tS[pl][lane + 32];
        float m = fmaxf(tM[pl][lane], tM[pl][lane + 32]);
#pragma unroll
        for (int o = 16; o; o >>= 1) {
            s += __shfl_xor_sync(0xFFFFFFFFu, s, o);
            m = fmaxf(m, __shfl_xor_sync(0xFFFFFFFFu, m, o));
        }
        if (lane == 0) {
            float avg = s * (1.f / 4096.f);
            float u[4], um = -3.4e38f;
#pragma unroll
            for (int k = 0; k < 4; k++) {
                const float* mc = &g_Mc[(0 * KK + k) * 3];
                u[k] = mc[0] * avg + mc[1] * m + mc[2];
                um = fmaxf(um, u[k]);
            }
            float es = 0.f;
#pragma unroll
            for (int k = 0; k < 4; k++) { u[k] = expf(u[k] - um); es += u[k]; }
            float inv = 1.f / es;
#pragma unroll
            for (int k = 0; k < 4; k++) g_U1[(b * CC + c0 + pl) * 4 + k] = u[k] * inv;
        }
    }
}

// ---------------- modes finalize: reduce 256 c-partials, softmax ------------
__global__ __launch_bounds__(256) void modes_final_kernel() {
    int gw = blockIdx.x * 8 + (threadIdx.x >> 5);
    int lane = threadIdx.x & 31;
    int isU2 = (gw < 512);
    int e = isU2 ? gw : gw - 512;
    const float* pS = isU2 ? g_pcS : g_prS;
    const float* pM = isU2 ? g_pcM : g_prM;
    float s = 0.f, m = -3.4e38f;
#pragma unroll
    for (int it = 0; it < 8; it++) {
        int i = it * 32 + lane;
        s += pS[e * 256 + i];
        m = fmaxf(m, pM[e * 256 + i]);
    }
#pragma unroll
    for (int o = 16; o; o >>= 1) {
        s += __shfl_xor_sync(0xFFFFFFFFu, s, o);
        m = fmaxf(m, __shfl_xor_sync(0xFFFFFFFFu, m, o));
    }
    if (lane == 0) {
        float avg = s * (1.f / 16384.f);
        int mode = isU2 ? 1 : 2;
        float u[4], um = -3.4e38f;
#pragma unroll
        for (int k = 0; k < 4; k++) {
            const float* mc = &g_Mc[(mode * KK + k) * 3];
            u[k] = mc[0] * avg + mc[1] * m + mc[2];
            um = fmaxf(um, u[k]);
        }
        float es = 0.f;
#pragma unroll
        for (int k = 0; k < 4; k++) { u[k] = expf(u[k] - um); es += u[k]; }
        float inv = 1.f / es;
        float* U = isU2 ? g_U2 : g_U3;
#pragma unroll
        for (int k = 0; k < 4; k++) U[e * 4 + k] = u[k] * inv;
    }
}

// ---------------- K3: spatial, ga/gm, V1 (warp-parallel) --------------------
__global__ __launch_bounds__(256) void small_kernel(const float* __restrict__ Wr,
                                                    const float* __restrict__ lam,
                                                    const float* __restrict__ ws_p,
                                                    const float* __restrict__ bs_p) {
    const int bid = blockIdx.x, tid = threadIdx.x;
    const int wid = tid >> 5, lane = tid & 31;
    if (bid < 128) {
        int g = bid * 256 + tid;
        int b = g >> 12, p = g & 4095;
        int h = p >> 6, w = p & 63;
        float4 u3 = *(const float4*)&g_U3[(b * 64 + h) * 4];
        float4 u2 = *(const float4*)&g_U2[(b * 64 + w) * 4];
        float d = u3.x * u2.x + u3.y * u2.y + u3.z * u2.z + u3.w * u2.w;
        float v = ws_p[0] * d + bs_p[0];
        g_spatial[g] = sigm(v);
    } else if (bid < 384) {
        int g = (bid - 128) * 8 + wid;
        int b = g >> 8;
        float4 u1 = *(const float4*)&g_U1[(size_t)g * 4];
        float s = 0.f, m = -3.4e38f;
#pragma unroll
        for (int it = 0; it < 4; it++) {
            int n = it * 32 + lane;
            const float* uc = (n < 64) ? &g_U2[(b * 64 + n) * 4] : &g_U3[(b * 64 + n - 64) * 4];
            float4 u = *(const float4*)uc;
            float d = u1.x * u.x + u1.y * u.y + u1.z * u.z + u1.w * u.w;
            s += d; m = fmaxf(m, d);
        }
#pragma unroll
        for (int o = 16; o; o >>= 1) {
            s += __shfl_xor_sync(0xFFFFFFFFu, s, o);
            m = fmaxf(m, __shfl_xor_sync(0xFFFFFFFFu, m, o));
        }
        if (lane == 0) { g_ga[g] = s * (1.f / 128.f); g_gm[g] = m; }
    } else {
        int g = (bid - 384) * 8 + wid;
        int b = g >> 8, o = g & 255;
        float s0 = 0.f, s1 = 0.f, s2 = 0.f, s3 = 0.f;
#pragma unroll
        for (int it = 0; it < 8; it++) {
            int i = it * 32 + lane;
            float w = Wr[(size_t)o * CC + i];
            float4 u = *(const float4*)&g_U1[(size_t)(b * CC + i) * 4];
            s0 = fmaf(w, u.x, s0); s1 = fmaf(w, u.y, s1);
            s2 = fmaf(w, u.z, s2); s3 = fmaf(w, u.w, s3);
        }
#pragma unroll
        for (int o2 = 16; o2; o2 >>= 1) {
            s0 += __shfl_xor_sync(0xFFFFFFFFu, s0, o2);
            s1 += __shfl_xor_sync(0xFFFFFFFFu, s1, o2);
            s2 += __shfl_xor_sync(0xFFFFFFFFu, s2, o2);
            s3 += __shfl_xor_sync(0xFFFFFFFFu, s3, o2);
        }
        if (lane == 0) {
            float* v = &g_V1[(size_t)g * 4];
            v[0] = lam[0] * s0; v[1] = lam[1] * s1;
            v[2] = lam[2] * s2; v[3] = lam[3] * s3;
        }
    }
}

// ---------------- K4: spectral (warp-parallel) ------------------------------
__global__ __launch_bounds__(256) void spectral_kernel(const float* __restrict__ Wsa,
                                                       const float* __restrict__ bsa,
                                                       const float* __restrict__ Wsm,
                                                       const float* __restrict__ bsm) {
    int g = blockIdx.x * 8 + (threadIdx.x >> 5);
    int lane = threadIdx.x & 31;
    int b = g >> 8, o = g & 255;
    float s = 0.f;
#pragma unroll
    for (int it = 0; it < 8; it++) {
        int i = it * 32 + lane;
        s += Wsa[(size_t)o * CC + i] * g_ga[b * CC + i]
           + Wsm[(size_t)o * CC + i] * g_gm[b * CC + i];
    }
#pragma unroll
    for (int o2 = 16; o2; o2 >>= 1) s += __shfl_xor_sync(0xFFFFFFFFu, s, o2);
    if (lane == 0) {
        s += bsa[o] + bsm[o];
        g_spec[g] = sigm(sigm(s));
    }
}

// ---------------- K5: fused epilogue (8 elems/thread) -----------------------
// NOTE einsum "bcr,bhr,bwr": U2 is indexed by h, U3 by w.
__global__ __launch_bounds__(256) void epilogue_kernel(const float* __restrict__ frm,
                                                       const float* __restrict__ other,
                                                       const float* __restrict__ br,
                                                       const float* __restrict__ alpha_p,
                                                       float* __restrict__ out) {
    int e = blockIdx.x * 256 + threadIdx.x;
    int i8 = e * 8;
    int b = i8 >> 20;
    int c = (i8 >> 12) & 255;
    int h = (i8 >> 6) & 63;
    int w0 = i8 & 63;

    float alpha = alpha_p[0];
    float spec = g_spec[b * CC + c];
    const float* sp = &g_spatial[(b * HH + h) * WW + w0];

    float4 v1 = *(const float4*)&g_V1[(size_t)(b * CC + c) * 4];
    float4 u2h = *(const float4*)&g_U2[(b * 64 + h) * 4];
    float vr0 = v1.x * u2h.x, vr1 = v1.y * u2h.y;
    float vr2 = v1.z * u2h.z, vr3 = v1.w * u2h.w;
    float brc = br[c];

    uint4 mraw = *(const uint4*)&g_Fm[i8];
    float2 m01 = __half22float2(*(__half2*)&mraw.x);
    float2 m23 = __half22float2(*(__half2*)&mraw.y);
    float2 m45 = __half22float2(*(__half2*)&mraw.z);
    float2 m67 = __half22float2(*(__half2*)&mraw.w);
    float fm[8] = { m01.x, m01.y, m23.x, m23.y, m45.x, m45.y, m67.x, m67.y };

#pragma unroll
    for (int half8 = 0; half8 < 2; half8++) {
        int i4 = i8 + half8 * 4;
        float4 f4 = *(const float4*)&frm[i4];
        float4 o4 = *(const float4*)&other[i4];
        float fr[4] = { f4.x, f4.y, f4.z, f4.w };
        float ot[4] = { o4.x, o4.y, o4.z, o4.w };
        float fu[4], cr[4];
#pragma unroll
        for (int j = 0; j < 4; j++) {
            int wj = half8 * 4 + j;
            float wt = spec * sp[wj];
            fu[j] = alpha * wt * fr[j] + (1.f - alpha) * (1.f - wt) * ot[j];
            float4 u3w = *(const float4*)&g_U3[(b * 64 + w0 + wj) * 4];
            float cp = brc + vr0 * u3w.x + vr1 * u3w.y + vr2 * u3w.z + vr3 * u3w.w;
            cr[j] = cp * wt + fm[wj];
        }
        *(float4*)&out[i4] = make_float4(fu[0], fu[1], fu[2], fu[3]);
        *(float4*)&out[NOUT + i4] = make_float4(cr[0], cr[1], cr[2], cr[3]);
    }
}

// ---------------- launch -----------------------------------------------------
extern "C" void kernel_launch(void* const* d_in, const int* in_sizes, int n_in,
                              void* d_out, int out_size) {
    const float* frm   = (const float*)d_in[0];
    const float* other = (const float*)d_in[1];
    const float* W3    = (const float*)d_in[2];
    const float* b3    = (const float*)d_in[3];
    const float* Wa1   = (const float*)d_in[4];
    const float* ba1   = (const float*)d_in[5];
    const float* Wa2   = (const float*)d_in[6];
    const float* ba2   = (const float*)d_in[7];
    const float* Wa3   = (const float*)d_in[8];
    const float* ba3   = (const float*)d_in[9];
    const float* Wu    = (const float*)d_in[10];
    const float* bu    = (const float*)d_in[11];
    const float* Wr    = (const float*)d_in[12];
    const float* br    = (const float*)d_in[13];
    const float* ws    = (const float*)d_in[14];
    const float* bs    = (const float*)d_in[15];
    const float* Wsa   = (const float*)d_in[16];
    const float* bsa   = (const float*)d_in[17];
    const float* Wsm   = (const float*)d_in[18];
    const float* bsm   = (const float*)d_in[19];
    const float* alpha = (const float*)d_in[20];
    const float* lam   = (const float*)d_in[21];
    float* out = (float*)d_out;

    prep_w_kernel<<<dim3(18, 256), 256>>>(W3, Wu, bu, Wa1, ba1, Wa2, ba2, Wa3, ba3);
    prep_x_kernel<<<dim3(512, 8), 256>>>(frm, other);

    cudaFuncSetAttribute(conv_mma_kernel, cudaFuncAttributeMaxDynamicSharedMemorySize, DSMEM_BYTES);
    conv_mma_kernel<<<dim3(128, 2), 512, DSMEM_BYTES>>>(b3);

    modes_pass1_kernel<<<1024, 256>>>();
    modes_final_kernel<<<128, 256>>>();
    small_kernel<<<640, 256>>>(Wr, lam, ws, bs);
    spectral_kernel<<<256, 256>>>(Wsa, bsa, Wsm, bsm);
    epilogue_kernel<<<NOUT / 8 / 256, 256>>>(frm, other, br, alpha, out);
}

// round 16
// speedup vs baseline: 1.0640x; 1.0640x over previous
#include <cuda_runtime.h>
#include <cuda_fp16.h>
#include <math.h>
#include <stdint.h>

// Problem constants
#define BN 8
#define CC 256
#define CI 512        // 2C
#define HH 64
#define WW 64
#define KK 4
#define HW (HH*WW)          // 4096
#define CHW (CC*HW)         // 1048576
#define NOUT (BN*CHW)       // 8388608 per tensor
#define KTOT 4608           // CI*9
#define WSCALE 1024.0f
#define INV_WSCALE (1.0f/1024.0f)

// ---------------- scratch (device globals; no allocation allowed) ----------
__device__ __half g_Fm[NOUT];                       // conv+leaky output (fp16 NCHW)
__device__ __half g_Xh[BN*HH*WW*CI];                // NHWC fp16 image
__device__ __half g_Wh[CC*KTOT];                    // [co][tap*512+ci] (w*1024) fp16
__device__ float g_U1[BN*CC*KK];
__device__ float g_U2[BN*WW*KK];
__device__ float g_U3[BN*HH*KK];
__device__ float g_Mc[3*KK*3];
__device__ float g_spatial[BN*HW];
__device__ float g_spec[BN*CC];
__device__ float g_ga[BN*CC];
__device__ float g_gm[BN*CC];
__device__ float g_V1[BN*CC*KK];
// mode pooling partials: [b][n][c] layout (n = h or w)
__device__ float g_prS[BN*64*256];
__device__ float g_prM[BN*64*256];
__device__ float g_pcS[BN*64*256];
__device__ float g_pcM[BN*64*256];

// ================= PTX helpers ==============================================
__device__ __forceinline__ uint32_t smem_u32(const void* p) {
    uint32_t a;
    asm("{ .reg .u64 t; cvta.to.shared.u64 t, %1; cvt.u32.u64 %0, t; }" : "=r"(a) : "l"(p));
    return a;
}
__device__ __forceinline__ void cp_async16(uint32_t dst, const void* src, uint32_t srcSize) {
    asm volatile("cp.async.ca.shared.global [%0], [%1], 16, %2;"
                 :: "r"(dst), "l"(src), "r"(srcSize) : "memory");
}
#define CP_COMMIT() asm volatile("cp.async.commit_group;" ::: "memory")
#define CP_WAIT(n)  asm volatile("cp.async.wait_group %0;" :: "n"(n) : "memory")

__device__ __forceinline__ void ldsm4(uint32_t addr, uint32_t r[4]) {
    asm volatile("ldmatrix.sync.aligned.m8n8.x4.shared.b16 {%0,%1,%2,%3}, [%4];"
                 : "=r"(r[0]), "=r"(r[1]), "=r"(r[2]), "=r"(r[3]) : "r"(addr));
}
__device__ __forceinline__ void mma16816(float c[4], const uint32_t a[4], const uint32_t b[2]) {
    asm volatile("mma.sync.aligned.m16n8k16.row.col.f32.f16.f16.f32 "
                 "{%0,%1,%2,%3}, {%4,%5,%6,%7}, {%8,%9}, {%0,%1,%2,%3};"
                 : "+f"(c[0]), "+f"(c[1]), "+f"(c[2]), "+f"(c[3])
                 : "r"(a[0]), "r"(a[1]), "r"(a[2]), "r"(a[3]), "r"(b[0]), "r"(b[1]));
}
#define SWZ(x) ((x) ^ (((x) >> 3) & 0x70))
__device__ __forceinline__ float sigm(float x) { return 1.f / (1.f + expf(-x)); }

// ---------------- prep: weights*1024 -> fp16; block(0,0) also folds adapters -
__global__ __launch_bounds__(256) void prep_w_kernel(
    const float* __restrict__ W3,
    const float* __restrict__ Wu, const float* __restrict__ bu,
    const float* __restrict__ Wa1, const float* __restrict__ ba1,
    const float* __restrict__ Wa2, const float* __restrict__ ba2,
    const float* __restrict__ Wa3, const float* __restrict__ ba3) {
    int co = blockIdx.y;
    int r = blockIdx.x * 256 + threadIdx.x;   // 0..4607
    int tap = r >> 9, ci = r & 511;
    float v = W3[((size_t)co * CI + ci) * 9 + tap] * WSCALE;
    g_Wh[(size_t)co * KTOT + r] = __float2half_rn(v);

    if (blockIdx.x == 0 && blockIdx.y == 0 && threadIdx.x < 12) {
        int t = threadIdx.x;
        int m = t >> 2, k = t & 3;
        const float* Wa = (m == 0) ? Wa1 : ((m == 1) ? Wa2 : Wa3);
        const float* ba = (m == 0) ? ba1 : ((m == 1) ? ba2 : ba3);
        float m0 = 0.f, m1 = 0.f, cc = 0.f;
        for (int o = 0; o < CC; o++) {
            float wu = Wu[k * CC + o];
            m0 += wu * Wa[o * 2 + 0];
            m1 += wu * Wa[o * 2 + 1];
            cc += wu * ba[o];
        }
        g_Mc[(m * KK + k) * 3 + 0] = m0;
        g_Mc[(m * KK + k) * 3 + 1] = m1;
        g_Mc[(m * KK + k) * 3 + 2] = cc + bu[k];
    }
}

// ---------------- prep: inputs NCHW fp32 -> NHWC fp16 -----------------------
__global__ __launch_bounds__(256) void prep_x_kernel(const float* __restrict__ frm,
                                                     const float* __restrict__ other) {
    __shared__ float S[64][65];
    int by = blockIdx.x;           // b*64 + y
    int b = by >> 6, y = by & 63;
    int cc = blockIdx.y;           // ci chunk of 64
    int tid = threadIdx.x;
#pragma unroll
    for (int i = 0; i < 16; i++) {
        int idx = i * 256 + tid;
        int ciL = idx >> 6, x = idx & 63;
        int ciX = cc * 64 + ciL;
        const float* src = (ciX < CC) ? frm : other;
        int cs = ciX & 255;
        S[ciL][x] = src[((size_t)(b * CC + cs) * HH + y) * WW + x];
    }
    __syncthreads();
#pragma unroll
    for (int i = 0; i < 16; i++) {
        int idx = i * 256 + tid;
        int x = idx >> 6, ciL = idx & 63;
        size_t d = ((size_t)(b * 64 + y) * 64 + x) * CI + cc * 64 + ciL;
        g_Xh[d] = __float2half_rn(S[ciL][x]);
    }
}

// ---------------- conv via mma.sync fp16 implicit GEMM ----------------------
#define STAGE_B 98304
#define A_SUB   32768
#define B_OFF   65536
#define B_SUB   16384
#define DSMEM_BYTES (2*STAGE_B + 1024)

__device__ __forceinline__ void stage_load64(uint32_t aBase, uint32_t bBase,
                                             int m0, int co0, int oc, int tid) {
    const int tap = oc >> 3, cic = oc & 7;
    const int ky = tap / 3 - 1, kx = tap % 3 - 1;
    const int ci0 = cic * 64;
#pragma unroll
    for (int it = 0; it < 4; it++) {
        int idx = it * 512 + tid;
        int r = idx >> 3, q = idx & 7;
        int p = m0 + r;
        int b = p >> 12;
        int ys = ((p >> 6) & 63) + ky, xs = (p & 63) + kx;
        bool ok = ((unsigned)ys < 64u) && ((unsigned)xs < 64u);
        const void* src = ok
            ? (const void*)(g_Xh + (((size_t)(b * 64 + ys) * 64 + xs) * CI + ci0 + q * 8))
            : (const void*)g_Xh;
        uint32_t full = (uint32_t)(r * 128 + q * 16);
        cp_async16(aBase + SWZ(full), src, ok ? 16u : 0u);
    }
#pragma unroll
    for (int it = 0; it < 2; it++) {
        int idx = it * 512 + tid;
        int r = idx >> 3, q = idx & 7;
        const void* src = g_Wh + ((size_t)(co0 + r) * KTOT + oc * 64 + q * 8);
        uint32_t full = (uint32_t)(r * 128 + q * 16);
        cp_async16(bBase + SWZ(full), src, 16u);
    }
}

__device__ __forceinline__ void stage_load128(uint32_t smStage, int m0, int co0,
                                              int c36, int tid) {
    stage_load64(smStage,         smStage + B_OFF,         m0, co0, 2 * c36,     tid);
    stage_load64(smStage + A_SUB, smStage + B_OFF + B_SUB, m0, co0, 2 * c36 + 1, tid);
}

__global__ __launch_bounds__(512, 1)
void conv_mma_kernel(const float* __restrict__ b3) {
    extern __shared__ __align__(128) char dynsm_raw[];
    const uint32_t smBase = (smem_u32(dynsm_raw) + 1023) & ~1023u;

    const int tid = threadIdx.x;
    const int lane = tid & 31;
    const int w = tid >> 5;
    const int wm = w & 3, wn = w >> 2;
    const int m0 = (int)blockIdx.x * 256;
    const int co0 = (int)blockIdx.y * 128;

    float acc[4][4][4];
#pragma unroll
    for (int mf = 0; mf < 4; mf++)
#pragma unroll
        for (int nf = 0; nf < 4; nf++)
#pragma unroll
            for (int j = 0; j < 4; j++) acc[mf][nf][j] = 0.f;

    const uint32_t aRowOff = (uint32_t)((wm * 64 + (lane & 15)) * 128);
    const uint32_t aColB   = (uint32_t)((lane >> 4) * 16);
    const uint32_t bRowOff = (uint32_t)((wn * 32 + (lane & 7) + ((lane >> 4) << 3)) * 128);
    const uint32_t bColB   = (uint32_t)(((lane >> 3) & 1) * 16);

    stage_load128(smBase, m0, co0, 0, tid);
    CP_COMMIT();

    for (int c = 0; c < 36; c++) {
        CP_WAIT(0);
        __syncthreads();

        if (c + 1 < 36) {
            stage_load128(smBase + (uint32_t)((c + 1) & 1) * STAGE_B, m0, co0, c + 1, tid);
            CP_COMMIT();
        }

        const uint32_t st = smBase + (uint32_t)(c & 1) * STAGE_B;
#pragma unroll
        for (int sub = 0; sub < 2; sub++) {
            const uint32_t aSt = st + (uint32_t)sub * A_SUB;
            const uint32_t bSt = st + B_OFF + (uint32_t)sub * B_SUB;
#pragma unroll
            for (int k16 = 0; k16 < 4; k16++) {
                const uint32_t kb = (uint32_t)(k16 * 32);
                uint32_t a[4][4], bb[4][2];
#pragma unroll
                for (int mf = 0; mf < 4; mf++) {
                    uint32_t aAddr = aSt + SWZ(aRowOff + (uint32_t)(mf * 2048) + aColB + kb);
                    ldsm4(aAddr, a[mf]);
                }
                {
                    uint32_t bAddr = bSt + SWZ(bRowOff + bColB + kb);
                    uint32_t rh[4];
                    ldsm4(bAddr, rh);
                    bb[0][0] = rh[0]; bb[0][1] = rh[1];
                    bb[1][0] = rh[2]; bb[1][1] = rh[3];
                    uint32_t bAddr2 = bSt + SWZ(bRowOff + 2048 + bColB + kb);
                    ldsm4(bAddr2, rh);
                    bb[2][0] = rh[0]; bb[2][1] = rh[1];
                    bb[3][0] = rh[2]; bb[3][1] = rh[3];
                }
#pragma unroll
                for (int mf = 0; mf < 4; mf++)
#pragma unroll
                    for (int nf = 0; nf < 4; nf++) mma16816(acc[mf][nf], a[mf], bb[nf]);
            }
        }
    }

    // epilogue: unscale + bias + leaky relu -> g_Fm (fp16 NCHW)
    const int rr = wm * 64 + (lane >> 2);
    const int ccb = co0 + wn * 32 + (lane & 3) * 2;
#pragma unroll
    for (int mf = 0; mf < 4; mf++) {
        int p = m0 + rr + mf * 16;
        int b = p >> 12;
        int pix = p & 4095;
#pragma unroll
        for (int nf = 0; nf < 4; nf++) {
            int co = ccb + nf * 8;
            float bi0 = __ldg(&b3[co]), bi1 = __ldg(&b3[co + 1]);
            float v0 = acc[mf][nf][0] * INV_WSCALE + bi0;
            float v1 = acc[mf][nf][1] * INV_WSCALE + bi1;
            float v2 = acc[mf][nf][2] * INV_WSCALE + bi0;
            float v3 = acc[mf][nf][3] * INV_WSCALE + bi1;
            v0 = (v0 > 0.f) ? v0 : 0.01f * v0;
            v1 = (v1 > 0.f) ? v1 : 0.01f * v1;
            v2 = (v2 > 0.f) ? v2 : 0.01f * v2;
            v3 = (v3 > 0.f) ? v3 : 0.01f * v3;
            size_t base0 = ((size_t)(b * CC + co) << 12) + pix;
            size_t base1 = ((size_t)(b * CC + co + 1) << 12) + pix;
            g_Fm[base0] = __float2half_rn(v0);
            g_Fm[base1] = __float2half_rn(v1);
            g_Fm[base0 + 8] = __float2half_rn(v2);
            g_Fm[base1 + 8] = __float2half_rn(v3);
        }
    }
}

// ---------------- modes pass1: smem-plane pooling over fp16 Fm --------------
__global__ __launch_bounds__(256) void modes_pass1_kernel() {
    const int bc = blockIdx.x;            // b*256 + c
    const int b = bc >> 8, c = bc & 255;
    const uint4* p = (const uint4*)(g_Fm + ((size_t)bc << 12));   // 512 uint4
    const int tid = threadIdx.x;

    __shared__ float S[64][65];
    __shared__ float rPS[4][64], rPM[4][64];
    __shared__ float cPS[4][64], cPM[4][64];
    __shared__ float tS[64], tM[64];

#pragma unroll
    for (int i = 0; i < 2; i++) {
        int idx = i * 256 + tid;
        uint4 v = p[idx];
        int r = idx >> 3, c8 = (idx & 7) * 8;
        float2 f0 = __half22float2(*(__half2*)&v.x);
        float2 f1 = __half22float2(*(__half2*)&v.y);
        float2 f2 = __half22float2(*(__half2*)&v.z);
        float2 f3 = __half22float2(*(__half2*)&v.w);
        S[r][c8 + 0] = f0.x; S[r][c8 + 1] = f0.y;
        S[r][c8 + 2] = f1.x; S[r][c8 + 3] = f1.y;
        S[r][c8 + 4] = f2.x; S[r][c8 + 5] = f2.y;
        S[r][c8 + 6] = f3.x; S[r][c8 + 7] = f3.y;
    }
    __syncthreads();

    {
        int r = tid & 63, sg = tid >> 6;
        const float* row = &S[r][sg * 16];
        float s = 0.f, m = -3.4e38f;
#pragma unroll
        for (int j = 0; j < 16; j++) { float v = row[j]; s += v; m = fmaxf(m, v); }
        rPS[sg][r] = s; rPM[sg][r] = m;
    }
    {
        int col = tid & 63, sg = tid >> 6;
        float s = 0.f, m = -3.4e38f;
#pragma unroll
        for (int j = 0; j < 16; j++) { float v = S[sg * 16 + j][col]; s += v; m = fmaxf(m, v); }
        cPS[sg][col] = s; cPM[sg][col] = m;
    }
    __syncthreads();

    if (tid < 64) {
        float s = rPS[0][tid] + rPS[1][tid] + rPS[2][tid] + rPS[3][tid];
        float m = fmaxf(fmaxf(rPM[0][tid], rPM[1][tid]), fmaxf(rPM[2][tid], rPM[3][tid]));
        g_prS[(b * 64 + tid) * 256 + c] = s;
        g_prM[(b * 64 + tid) * 256 + c] = m;
        tS[tid] = s; tM[tid] = m;
    } else if (tid < 128) {
        int wq = tid - 64;
        float s = cPS[0][wq] + cPS[1][wq] + cPS[2][wq] + cPS[3][wq];
        float m = fmaxf(fmaxf(cPM[0][wq], cPM[1][wq]), fmaxf(cPM[2][wq], cPM[3][wq]));
        g_pcS[(b * 64 + wq) * 256 + c] = s;
        g_pcM[(b * 64 + wq) * 256 + c] = m;
    }
    __syncthreads();

    if (tid < 32) {
        float s = tS[tid] + tS[tid + 32];
        float m = fmaxf(tM[tid], tM[tid + 32]);
#pragma unroll
        for (int o = 16; o; o >>= 1) {
            s += __shfl_xor_sync(0xFFFFFFFFu, s, o);
            m = fmaxf(m, __shfl_xor_sync(0xFFFFFFFFu, m, o));
        }
        if (tid == 0) {
            float avg = s * (1.f / 4096.f);
            float u[4], um = -3.4e38f;
#pragma unroll
            for (int k = 0; k < 4; k++) {
                const float* mc = &g_Mc[(0 * KK + k) * 3];
                u[k] = mc[0] * avg + mc[1] * m + mc[2];
                um = fmaxf(um, u[k]);
            }
            float es = 0.f;
#pragma unroll
            for (int k = 0; k < 4; k++) { u[k] = expf(u[k] - um); es += u[k]; }
            float inv = 1.f / es;
#pragma unroll
            for (int k = 0; k < 4; k++) g_U1[bc * 4 + k] = u[k] * inv;
        }
    }
}

// ---------------- modes finalize: reduce 256 c-partials, softmax ------------
__global__ __launch_bounds__(256) void modes_final_kernel() {
    int gw = blockIdx.x * 8 + (threadIdx.x >> 5);
    int lane = threadIdx.x & 31;
    int isU2 = (gw < 512);
    int e = isU2 ? gw : gw - 512;
    const float* pS = isU2 ? g_pcS : g_prS;
    const float* pM = isU2 ? g_pcM : g_prM;
    float s = 0.f, m = -3.4e38f;
#pragma unroll
    for (int it = 0; it < 8; it++) {
        int i = it * 32 + lane;
        s += pS[e * 256 + i];
        m = fmaxf(m, pM[e * 256 + i]);
    }
#pragma unroll
    for (int o = 16; o; o >>= 1) {
        s += __shfl_xor_sync(0xFFFFFFFFu, s, o);
        m = fmaxf(m, __shfl_xor_sync(0xFFFFFFFFu, m, o));
    }
    if (lane == 0) {
        float avg = s * (1.f / 16384.f);
        int mode = isU2 ? 1 : 2;
        float u[4], um = -3.4e38f;
#pragma unroll
        for (int k = 0; k < 4; k++) {
            const float* mc = &g_Mc[(mode * KK + k) * 3];
            u[k] = mc[0] * avg + mc[1] * m + mc[2];
            um = fmaxf(um, u[k]);
        }
        float es = 0.f;
#pragma unroll
        for (int k = 0; k < 4; k++) { u[k] = expf(u[k] - um); es += u[k]; }
        float inv = 1.f / es;
        float* U = isU2 ? g_U2 : g_U3;
#pragma unroll
        for (int k = 0; k < 4; k++) U[e * 4 + k] = u[k] * inv;
    }
}

// ---------------- K3: spatial, ga/gm, V1 (warp-parallel) --------------------
__global__ __launch_bounds__(256) void small_kernel(const float* __restrict__ Wr,
                                                    const float* __restrict__ lam,
                                                    const float* __restrict__ ws_p,
                                                    const float* __restrict__ bs_p) {
    const int bid = blockIdx.x, tid = threadIdx.x;
    const int wid = tid >> 5, lane = tid & 31;
    if (bid < 128) {
        int g = bid * 256 + tid;
        int b = g >> 12, p = g & 4095;
        int h = p >> 6, w = p & 63;
        float4 u3 = *(const float4*)&g_U3[(b * 64 + h) * 4];
        float4 u2 = *(const float4*)&g_U2[(b * 64 + w) * 4];
        float d = u3.x * u2.x + u3.y * u2.y + u3.z * u2.z + u3.w * u2.w;
        float v = ws_p[0] * d + bs_p[0];
        g_spatial[g] = sigm(v);
    } else if (bid < 384) {
        int g = (bid - 128) * 8 + wid;
        int b = g >> 8;
        float4 u1 = *(const float4*)&g_U1[(size_t)g * 4];
        float s = 0.f, m = -3.4e38f;
#pragma unroll
        for (int it = 0; it < 4; it++) {
            int n = it * 32 + lane;
            const float* uc = (n < 64) ? &g_U2[(b * 64 + n) * 4] : &g_U3[(b * 64 + n - 64) * 4];
            float4 u = *(const float4*)uc;
            float d = u1.x * u.x + u1.y * u.y + u1.z * u.z + u1.w * u.w;
            s += d; m = fmaxf(m, d);
        }
#pragma unroll
        for (int o = 16; o; o >>= 1) {
            s += __shfl_xor_sync(0xFFFFFFFFu, s, o);
            m = fmaxf(m, __shfl_xor_sync(0xFFFFFFFFu, m, o));
        }
        if (lane == 0) { g_ga[g] = s * (1.f / 128.f); g_gm[g] = m; }
    } else {
        int g = (bid - 384) * 8 + wid;
        int b = g >> 8, o = g & 255;
        float s0 = 0.f, s1 = 0.f, s2 = 0.f, s3 = 0.f;
#pragma unroll
        for (int it = 0; it < 8; it++) {
            int i = it * 32 + lane;
            float w = Wr[(size_t)o * CC + i];
            float4 u = *(const float4*)&g_U1[(size_t)(b * CC + i) * 4];
            s0 = fmaf(w, u.x, s0); s1 = fmaf(w, u.y, s1);
            s2 = fmaf(w, u.z, s2); s3 = fmaf(w, u.w, s3);
        }
#pragma unroll
        for (int o2 = 16; o2; o2 >>= 1) {
            s0 += __shfl_xor_sync(0xFFFFFFFFu, s0, o2);
            s1 += __shfl_xor_sync(0xFFFFFFFFu, s1, o2);
            s2 += __shfl_xor_sync(0xFFFFFFFFu, s2, o2);
            s3 += __shfl_xor_sync(0xFFFFFFFFu, s3, o2);
        }
        if (lane == 0) {
            float* v = &g_V1[(size_t)g * 4];
            v[0] = lam[0] * s0; v[1] = lam[1] * s1;
            v[2] = lam[2] * s2; v[3] = lam[3] * s3;
        }
    }
}

// ---------------- K4: spectral (warp-parallel) ------------------------------
__global__ __launch_bounds__(256) void spectral_kernel(const float* __restrict__ Wsa,
                                                       const float* __restrict__ bsa,
                                                       const float* __restrict__ Wsm,
                                                       const float* __restrict__ bsm) {
    int g = blockIdx.x * 8 + (threadIdx.x >> 5);
    int lane = threadIdx.x & 31;
    int b = g >> 8, o = g & 255;
    float s = 0.f;
#pragma unroll
    for (int it = 0; it < 8; it++) {
        int i = it * 32 + lane;
        s += Wsa[(size_t)o * CC + i] * g_ga[b * CC + i]
           + Wsm[(size_t)o * CC + i] * g_gm[b * CC + i];
    }
#pragma unroll
    for (int o2 = 16; o2; o2 >>= 1) s += __shfl_xor_sync(0xFFFFFFFFu, s, o2);
    if (lane == 0) {
        s += bsa[o] + bsm[o];
        g_spec[g] = sigm(sigm(s));
    }
}

// ---------------- K5: fused epilogue (both outputs) -------------------------
// NOTE einsum "bcr,bhr,bwr": U2 is indexed by h, U3 by w.
__global__ __launch_bounds__(256) void epilogue_kernel(const float* __restrict__ frm,
                                                       const float* __restrict__ other,
                                                       const float* __restrict__ br,
                                                       const float* __restrict__ alpha_p,
                                                       float* __restrict__ out) {
    int e = blockIdx.x * 256 + threadIdx.x;
    int i4 = e * 4;
    int b = i4 >> 20;
    int c = (i4 >> 12) & 255;
    int h = (i4 >> 6) & 63;
    int w0 = i4 & 63;

    float alpha = alpha_p[0];
    float spec = g_spec[b * CC + c];
    const float* sp = &g_spatial[(b * HH + h) * WW + w0];
    float4 f4 = *(const float4*)&frm[i4];
    float4 o4 = *(const float4*)&other[i4];
    uint2 mraw = *(const uint2*)&g_Fm[i4];
    float2 mlo = __half22float2(*(__half2*)&mraw.x);
    float2 mhi = __half22float2(*(__half2*)&mraw.y);

    float4 v1 = *(const float4*)&g_V1[(size_t)(b * CC + c) * 4];
    float4 u2h = *(const float4*)&g_U2[(b * 64 + h) * 4];
    float vr0 = v1.x * u2h.x, vr1 = v1.y * u2h.y;
    float vr2 = v1.z * u2h.z, vr3 = v1.w * u2h.w;
    float brc = br[c];

    float fu[4], cr[4];
    float fr[4] = { f4.x, f4.y, f4.z, f4.w };
    float ot[4] = { o4.x, o4.y, o4.z, o4.w };
    float fm[4] = { mlo.x, mlo.y, mhi.x, mhi.y };
#pragma unroll
    for (int j = 0; j < 4; j++) {
        float wt = spec * sp[j];
        fu[j] = alpha * wt * fr[j] + (1.f - alpha) * (1.f - wt) * ot[j];
        float4 u3w = *(const float4*)&g_U3[(b * 64 + w0 + j) * 4];
        float cp = brc + vr0 * u3w.x + vr1 * u3w.y + vr2 * u3w.z + vr3 * u3w.w;
        cr[j] = cp * wt + fm[j];
    }
    *(float4*)&out[i4] = make_float4(fu[0], fu[1], fu[2], fu[3]);
    *(float4*)&out[NOUT + i4] = make_float4(cr[0], cr[1], cr[2], cr[3]);
}

// ---------------- launch -----------------------------------------------------
extern "C" void kernel_launch(void* const* d_in, const int* in_sizes, int n_in,
                              void* d_out, int out_size) {
    const float* frm   = (const float*)d_in[0];
    const float* other = (const float*)d_in[1];
    const float* W3    = (const float*)d_in[2];
    const float* b3    = (const float*)d_in[3];
    const float* Wa1   = (const float*)d_in[4];
    const float* ba1   = (const float*)d_in[5];
    const float* Wa2   = (const float*)d_in[6];
    const float* ba2   = (const float*)d_in[7];
    const float* Wa3   = (const float*)d_in[8];
    const float* ba3   = (const float*)d_in[9];
    const float* Wu    = (const float*)d_in[10];
    const float* bu    = (const float*)d_in[11];
    const float* Wr    = (const float*)d_in[12];
    const float* br    = (const float*)d_in[13];
    const float* ws    = (const float*)d_in[14];
    const float* bs    = (const float*)d_in[15];
    const float* Wsa   = (const float*)d_in[16];
    const float* bsa   = (const float*)d_in[17];
    const float* Wsm   = (const float*)d_in[18];
    const float* bsm   = (const float*)d_in[19];
    const float* alpha = (const float*)d_in[20];
    const float* lam   = (const float*)d_in[21];
    float* out = (float*)d_out;

    prep_w_kernel<<<dim3(18, 256), 256>>>(W3, Wu, bu, Wa1, ba1, Wa2, ba2, Wa3, ba3);
    prep_x_kernel<<<dim3(512, 8), 256>>>(frm, other);

    cudaFuncSetAttribute(conv_mma_kernel, cudaFuncAttributeMaxDynamicSharedMemorySize, DSMEM_BYTES);
    conv_mma_kernel<<<dim3(128, 2), 512, DSMEM_BYTES>>>(b3);

    modes_pass1_kernel<<<2048, 256>>>();
    modes_final_kernel<<<128, 256>>>();
    small_kernel<<<640, 256>>>(Wr, lam, ws, bs);
    spectral_kernel<<<256, 256>>>(Wsa, bsa, Wsm, bsm);
    epilogue_kernel<<<NOUT / 4 / 256, 256>>>(frm, other, br, alpha, out);
}

// round 17
// speedup vs baseline: 1.1021x; 1.0358x over previous
#include <cuda_runtime.h>
#include <cuda_fp16.h>
#include <math.h>
#include <stdint.h>

// Problem constants
#define BN 8
#define CC 256
#define CI 512        // 2C
#define HH 64
#define WW 64
#define KK 4
#define HW (HH*WW)          // 4096
#define CHW (CC*HW)         // 1048576
#define NOUT (BN*CHW)       // 8388608 per tensor
#define KTOT 4608           // CI*9
#define WSCALE 1024.0f
#define INV_WSCALE (1.0f/1024.0f)

// ---------------- scratch (device globals; no allocation allowed) ----------
__device__ __half g_Fm[NOUT];                       // conv+leaky output (fp16 NCHW)
__device__ __half g_Xh[BN*HH*WW*CI];                // NHWC fp16 image
__device__ __half g_Wh[CC*KTOT];                    // [co][tap*512+ci] (w*1024) fp16
__device__ float g_U1[BN*CC*KK];
__device__ float g_U2[BN*WW*KK];
__device__ float g_U3[BN*HH*KK];
__device__ float g_Mc[3*KK*3];
__device__ float g_spatial[BN*HW];
__device__ float g_spec[BN*CC];
__device__ float g_ga[BN*CC];
__device__ float g_gm[BN*CC];
__device__ float g_V1[BN*CC*KK];
// mode pooling partials: [b][n][c] layout (n = h or w)
__device__ float g_prS[BN*64*256];
__device__ float g_prM[BN*64*256];
__device__ float g_pcS[BN*64*256];
__device__ float g_pcM[BN*64*256];

// ================= PTX helpers ==============================================
__device__ __forceinline__ uint32_t smem_u32(const void* p) {
    uint32_t a;
    asm("{ .reg .u64 t; cvta.to.shared.u64 t, %1; cvt.u32.u64 %0, t; }" : "=r"(a) : "l"(p));
    return a;
}
__device__ __forceinline__ void cp_async16(uint32_t dst, const void* src, uint32_t srcSize) {
    asm volatile("cp.async.ca.shared.global [%0], [%1], 16, %2;"
                 :: "r"(dst), "l"(src), "r"(srcSize) : "memory");
}
#define CP_COMMIT() asm volatile("cp.async.commit_group;" ::: "memory")
#define CP_WAIT(n)  asm volatile("cp.async.wait_group %0;" :: "n"(n) : "memory")

__device__ __forceinline__ void ldsm4(uint32_t addr, uint32_t r[4]) {
    asm volatile("ldmatrix.sync.aligned.m8n8.x4.shared.b16 {%0,%1,%2,%3}, [%4];"
                 : "=r"(r[0]), "=r"(r[1]), "=r"(r[2]), "=r"(r[3]) : "r"(addr));
}
__device__ __forceinline__ void mma16816(float c[4], const uint32_t a[4], const uint32_t b[2]) {
    asm volatile("mma.sync.aligned.m16n8k16.row.col.f32.f16.f16.f32 "
                 "{%0,%1,%2,%3}, {%4,%5,%6,%7}, {%8,%9}, {%0,%1,%2,%3};"
                 : "+f"(c[0]), "+f"(c[1]), "+f"(c[2]), "+f"(c[3])
                 : "r"(a[0]), "r"(a[1]), "r"(a[2]), "r"(a[3]), "r"(b[0]), "r"(b[1]));
}
#define SWZ(x) ((x) ^ (((x) >> 3) & 0x70))
__device__ __forceinline__ float sigm(float x) { return 1.f / (1.f + expf(-x)); }

// ---------------- fused prep: weights + inputs + adapter fold ---------------
// blocks [0, 4608): prep_w  (co = bid/18, r = (bid%18)*256+tid)
// blocks [4608, 8704): prep_x (rem = bid-4608; by = rem>>3, cc = rem&7)
#define PW_BLOCKS 4608
__global__ __launch_bounds__(256) void prep_kernel(
    const float* __restrict__ W3,
    const float* __restrict__ frm, const float* __restrict__ other,
    const float* __restrict__ Wu, const float* __restrict__ bu,
    const float* __restrict__ Wa1, const float* __restrict__ ba1,
    const float* __restrict__ Wa2, const float* __restrict__ ba2,
    const float* __restrict__ Wa3, const float* __restrict__ ba3) {
    __shared__ float S[64][65];
    const int bid = blockIdx.x;
    const int tid = threadIdx.x;

    if (bid < PW_BLOCKS) {
        int co = bid / 18;
        int r = (bid - co * 18) * 256 + tid;   // 0..4607
        int tap = r >> 9, ci = r & 511;
        float v = W3[((size_t)co * CI + ci) * 9 + tap] * WSCALE;
        g_Wh[(size_t)co * KTOT + r] = __float2half_rn(v);

        if (bid == 0 && tid < 12) {
            int t = tid;
            int m = t >> 2, k = t & 3;
            const float* Wa = (m == 0) ? Wa1 : ((m == 1) ? Wa2 : Wa3);
            const float* ba = (m == 0) ? ba1 : ((m == 1) ? ba2 : ba3);
            float m0 = 0.f, m1 = 0.f, cc2 = 0.f;
            for (int o = 0; o < CC; o++) {
                float wu = Wu[k * CC + o];
                m0 += wu * Wa[o * 2 + 0];
                m1 += wu * Wa[o * 2 + 1];
                cc2 += wu * ba[o];
            }
            g_Mc[(m * KK + k) * 3 + 0] = m0;
            g_Mc[(m * KK + k) * 3 + 1] = m1;
            g_Mc[(m * KK + k) * 3 + 2] = cc2 + bu[k];
        }
        return;
    }

    // ---- prep_x path ----
    int rem = bid - PW_BLOCKS;         // 0..4095
    int by = rem >> 3;                 // b*64 + y
    int cc = rem & 7;                  // ci chunk of 64
    int b = by >> 6, y = by & 63;
#pragma unroll
    for (int i = 0; i < 16; i++) {
        int idx = i * 256 + tid;
        int ciL = idx >> 6, x = idx & 63;
        int ciX = cc * 64 + ciL;
        const float* src = (ciX < CC) ? frm : other;
        int cs = ciX & 255;
        S[ciL][x] = src[((size_t)(b * CC + cs) * HH + y) * WW + x];
    }
    __syncthreads();
#pragma unroll
    for (int i = 0; i < 16; i++) {
        int idx = i * 256 + tid;
        int x = idx >> 6, ciL = idx & 63;
        size_t d = ((size_t)(b * 64 + y) * 64 + x) * CI + cc * 64 + ciL;
        g_Xh[d] = __float2half_rn(S[ciL][x]);
    }
}

// ---------------- conv via mma.sync fp16 implicit GEMM ----------------------
#define STAGE_B 98304
#define A_SUB   32768
#define B_OFF   65536
#define B_SUB   16384
#define DSMEM_BYTES (2*STAGE_B + 1024)

__device__ __forceinline__ void stage_load64(uint32_t aBase, uint32_t bBase,
                                             int m0, int co0, int oc, int tid) {
    const int tap = oc >> 3, cic = oc & 7;
    const int ky = tap / 3 - 1, kx = tap % 3 - 1;
    const int ci0 = cic * 64;
#pragma unroll
    for (int it = 0; it < 4; it++) {
        int idx = it * 512 + tid;
        int r = idx >> 3, q = idx & 7;
        int p = m0 + r;
        int b = p >> 12;
        int ys = ((p >> 6) & 63) + ky, xs = (p & 63) + kx;
        bool ok = ((unsigned)ys < 64u) && ((unsigned)xs < 64u);
        const void* src = ok
            ? (const void*)(g_Xh + (((size_t)(b * 64 + ys) * 64 + xs) * CI + ci0 + q * 8))
            : (const void*)g_Xh;
        uint32_t full = (uint32_t)(r * 128 + q * 16);
        cp_async16(aBase + SWZ(full), src, ok ? 16u : 0u);
    }
#pragma unroll
    for (int it = 0; it < 2; it++) {
        int idx = it * 512 + tid;
        int r = idx >> 3, q = idx & 7;
        const void* src = g_Wh + ((size_t)(co0 + r) * KTOT + oc * 64 + q * 8);
        uint32_t full = (uint32_t)(r * 128 + q * 16);
        cp_async16(bBase + SWZ(full), src, 16u);
    }
}

__device__ __forceinline__ void stage_load128(uint32_t smStage, int m0, int co0,
                                              int c36, int tid) {
    stage_load64(smStage,         smStage + B_OFF,         m0, co0, 2 * c36,     tid);
    stage_load64(smStage + A_SUB, smStage + B_OFF + B_SUB, m0, co0, 2 * c36 + 1, tid);
}

__global__ __launch_bounds__(512, 1)
void conv_mma_kernel(const float* __restrict__ b3) {
    extern __shared__ __align__(128) char dynsm_raw[];
    const uint32_t smBase = (smem_u32(dynsm_raw) + 1023) & ~1023u;

    const int tid = threadIdx.x;
    const int lane = tid & 31;
    const int w = tid >> 5;
    const int wm = w & 3, wn = w >> 2;
    const int m0 = (int)blockIdx.x * 256;
    const int co0 = (int)blockIdx.y * 128;

    float acc[4][4][4];
#pragma unroll
    for (int mf = 0; mf < 4; mf++)
#pragma unroll
        for (int nf = 0; nf < 4; nf++)
#pragma unroll
            for (int j = 0; j < 4; j++) acc[mf][nf][j] = 0.f;

    const uint32_t aRowOff = (uint32_t)((wm * 64 + (lane & 15)) * 128);
    const uint32_t aColB   = (uint32_t)((lane >> 4) * 16);
    const uint32_t bRowOff = (uint32_t)((wn * 32 + (lane & 7) + ((lane >> 4) << 3)) * 128);
    const uint32_t bColB   = (uint32_t)(((lane >> 3) & 1) * 16);

    stage_load128(smBase, m0, co0, 0, tid);
    CP_COMMIT();

    for (int c = 0; c < 36; c++) {
        CP_WAIT(0);
        __syncthreads();

        if (c + 1 < 36) {
            stage_load128(smBase + (uint32_t)((c + 1) & 1) * STAGE_B, m0, co0, c + 1, tid);
            CP_COMMIT();
        }

        const uint32_t st = smBase + (uint32_t)(c & 1) * STAGE_B;
#pragma unroll
        for (int sub = 0; sub < 2; sub++) {
            const uint32_t aSt = st + (uint32_t)sub * A_SUB;
            const uint32_t bSt = st + B_OFF + (uint32_t)sub * B_SUB;
#pragma unroll
            for (int k16 = 0; k16 < 4; k16++) {
                const uint32_t kb = (uint32_t)(k16 * 32);
                uint32_t a[4][4], bb[4][2];
#pragma unroll
                for (int mf = 0; mf < 4; mf++) {
                    uint32_t aAddr = aSt + SWZ(aRowOff + (uint32_t)(mf * 2048) + aColB + kb);
                    ldsm4(aAddr, a[mf]);
                }
                {
                    uint32_t bAddr = bSt + SWZ(bRowOff + bColB + kb);
                    uint32_t rh[4];
                    ldsm4(bAddr, rh);
                    bb[0][0] = rh[0]; bb[0][1] = rh[1];
                    bb[1][0] = rh[2]; bb[1][1] = rh[3];
                    uint32_t bAddr2 = bSt + SWZ(bRowOff + 2048 + bColB + kb);
                    ldsm4(bAddr2, rh);
                    bb[2][0] = rh[0]; bb[2][1] = rh[1];
                    bb[3][0] = rh[2]; bb[3][1] = rh[3];
                }
#pragma unroll
                for (int mf = 0; mf < 4; mf++)
#pragma unroll
                    for (int nf = 0; nf < 4; nf++) mma16816(acc[mf][nf], a[mf], bb[nf]);
            }
        }
    }

    // epilogue: unscale + bias + leaky relu -> g_Fm (fp16 NCHW)
    const int rr = wm * 64 + (lane >> 2);
    const int ccb = co0 + wn * 32 + (lane & 3) * 2;
#pragma unroll
    for (int mf = 0; mf < 4; mf++) {
        int p = m0 + rr + mf * 16;
        int b = p >> 12;
        int pix = p & 4095;
#pragma unroll
        for (int nf = 0; nf < 4; nf++) {
            int co = ccb + nf * 8;
            float bi0 = __ldg(&b3[co]), bi1 = __ldg(&b3[co + 1]);
            float v0 = acc[mf][nf][0] * INV_WSCALE + bi0;
            float v1 = acc[mf][nf][1] * INV_WSCALE + bi1;
            float v2 = acc[mf][nf][2] * INV_WSCALE + bi0;
            float v3 = acc[mf][nf][3] * INV_WSCALE + bi1;
            v0 = (v0 > 0.f) ? v0 : 0.01f * v0;
            v1 = (v1 > 0.f) ? v1 : 0.01f * v1;
            v2 = (v2 > 0.f) ? v2 : 0.01f * v2;
            v3 = (v3 > 0.f) ? v3 : 0.01f * v3;
            size_t base0 = ((size_t)(b * CC + co) << 12) + pix;
            size_t base1 = ((size_t)(b * CC + co + 1) << 12) + pix;
            g_Fm[base0] = __float2half_rn(v0);
            g_Fm[base1] = __float2half_rn(v1);
            g_Fm[base0 + 8] = __float2half_rn(v2);
            g_Fm[base1 + 8] = __float2half_rn(v3);
        }
    }
}

// ---------------- modes pass1: smem-plane pooling over fp16 Fm --------------
__global__ __launch_bounds__(256) void modes_pass1_kernel() {
    const int bc = blockIdx.x;            // b*256 + c
    const int b = bc >> 8, c = bc & 255;
    const uint4* p = (const uint4*)(g_Fm + ((size_t)bc << 12));   // 512 uint4
    const int tid = threadIdx.x;

    __shared__ float S[64][65];
    __shared__ float rPS[4][64], rPM[4][64];
    __shared__ float cPS[4][64], cPM[4][64];
    __shared__ float tS[64], tM[64];

#pragma unroll
    for (int i = 0; i < 2; i++) {
        int idx = i * 256 + tid;
        uint4 v = p[idx];
        int r = idx >> 3, c8 = (idx & 7) * 8;
        float2 f0 = __half22float2(*(__half2*)&v.x);
        float2 f1 = __half22float2(*(__half2*)&v.y);
        float2 f2 = __half22float2(*(__half2*)&v.z);
        float2 f3 = __half22float2(*(__half2*)&v.w);
        S[r][c8 + 0] = f0.x; S[r][c8 + 1] = f0.y;
        S[r][c8 + 2] = f1.x; S[r][c8 + 3] = f1.y;
        S[r][c8 + 4] = f2.x; S[r][c8 + 5] = f2.y;
        S[r][c8 + 6] = f3.x; S[r][c8 + 7] = f3.y;
    }
    __syncthreads();

    {
        int r = tid & 63, sg = tid >> 6;
        const float* row = &S[r][sg * 16];
        float s = 0.f, m = -3.4e38f;
#pragma unroll
        for (int j = 0; j < 16; j++) { float v = row[j]; s += v; m = fmaxf(m, v); }
        rPS[sg][r] = s; rPM[sg][r] = m;
    }
    {
        int col = tid & 63, sg = tid >> 6;
        float s = 0.f, m = -3.4e38f;
#pragma unroll
        for (int j = 0; j < 16; j++) { float v = S[sg * 16 + j][col]; s += v; m = fmaxf(m, v); }
        cPS[sg][col] = s; cPM[sg][col] = m;
    }
    __syncthreads();

    if (tid < 64) {
        float s = rPS[0][tid] + rPS[1][tid] + rPS[2][tid] + rPS[3][tid];
        float m = fmaxf(fmaxf(rPM[0][tid], rPM[1][tid]), fmaxf(rPM[2][tid], rPM[3][tid]));
        g_prS[(b * 64 + tid) * 256 + c] = s;
        g_prM[(b * 64 + tid) * 256 + c] = m;
        tS[tid] = s; tM[tid] = m;
    } else if (tid < 128) {
        int wq = tid - 64;
        float s = cPS[0][wq] + cPS[1][wq] + cPS[2][wq] + cPS[3][wq];
        float m = fmaxf(fmaxf(cPM[0][wq], cPM[1][wq]), fmaxf(cPM[2][wq], cPM[3][wq]));
        g_pcS[(b * 64 + wq) * 256 + c] = s;
        g_pcM[(b * 64 + wq) * 256 + c] = m;
    }
    __syncthreads();

    if (tid < 32) {
        float s = tS[tid] + tS[tid + 32];
        float m = fmaxf(tM[tid], tM[tid + 32]);
#pragma unroll
        for (int o = 16; o; o >>= 1) {
            s += __shfl_xor_sync(0xFFFFFFFFu, s, o);
            m = fmaxf(m, __shfl_xor_sync(0xFFFFFFFFu, m, o));
        }
        if (tid == 0) {
            float avg = s * (1.f / 4096.f);
            float u[4], um = -3.4e38f;
#pragma unroll
            for (int k = 0; k < 4; k++) {
                const float* mc = &g_Mc[(0 * KK + k) * 3];
                u[k] = mc[0] * avg + mc[1] * m + mc[2];
                um = fmaxf(um, u[k]);
            }
            float es = 0.f;
#pragma unroll
            for (int k = 0; k < 4; k++) { u[k] = expf(u[k] - um); es += u[k]; }
            float inv = 1.f / es;
#pragma unroll
            for (int k = 0; k < 4; k++) g_U1[bc * 4 + k] = u[k] * inv;
        }
    }
}

// ---------------- modes finalize: reduce 256 c-partials, softmax ------------
__global__ __launch_bounds__(256) void modes_final_kernel() {
    int gw = blockIdx.x * 8 + (threadIdx.x >> 5);
    int lane = threadIdx.x & 31;
    int isU2 = (gw < 512);
    int e = isU2 ? gw : gw - 512;
    const float* pS = isU2 ? g_pcS : g_prS;
    const float* pM = isU2 ? g_pcM : g_prM;
    float s = 0.f, m = -3.4e38f;
#pragma unroll
    for (int it = 0; it < 8; it++) {
        int i = it * 32 + lane;
        s += pS[e * 256 + i];
        m = fmaxf(m, pM[e * 256 + i]);
    }
#pragma unroll
    for (int o = 16; o; o >>= 1) {
        s += __shfl_xor_sync(0xFFFFFFFFu, s, o);
        m = fmaxf(m, __shfl_xor_sync(0xFFFFFFFFu, m, o));
    }
    if (lane == 0) {
        float avg = s * (1.f / 16384.f);
        int mode = isU2 ? 1 : 2;
        float u[4], um = -3.4e38f;
#pragma unroll
        for (int k = 0; k < 4; k++) {
            const float* mc = &g_Mc[(mode * KK + k) * 3];
            u[k] = mc[0] * avg + mc[1] * m + mc[2];
            um = fmaxf(um, u[k]);
        }
        float es = 0.f;
#pragma unroll
        for (int k = 0; k < 4; k++) { u[k] = expf(u[k] - um); es += u[k]; }
        float inv = 1.f / es;
        float* U = isU2 ? g_U2 : g_U3;
#pragma unroll
        for (int k = 0; k < 4; k++) U[e * 4 + k] = u[k] * inv;
    }
}

// ---------------- K3: spatial, ga/gm, V1 (warp-parallel) --------------------
__global__ __launch_bounds__(256) void small_kernel(const float* __restrict__ Wr,
                                                    const float* __restrict__ lam,
                                                    const float* __restrict__ ws_p,
                                                    const float* __restrict__ bs_p) {
    const int bid = blockIdx.x, tid = threadIdx.x;
    const int wid = tid >> 5, lane = tid & 31;
    if (bid < 128) {
        int g = bid * 256 + tid;
        int b = g >> 12, p = g & 4095;
        int h = p >> 6, w = p & 63;
        float4 u3 = *(const float4*)&g_U3[(b * 64 + h) * 4];
        float4 u2 = *(const float4*)&g_U2[(b * 64 + w) * 4];
        float d = u3.x * u2.x + u3.y * u2.y + u3.z * u2.z + u3.w * u2.w;
        float v = ws_p[0] * d + bs_p[0];
        g_spatial[g] = sigm(v);
    } else if (bid < 384) {
        int g = (bid - 128) * 8 + wid;
        int b = g >> 8;
        float4 u1 = *(const float4*)&g_U1[(size_t)g * 4];
        float s = 0.f, m = -3.4e38f;
#pragma unroll
        for (int it = 0; it < 4; it++) {
            int n = it * 32 + lane;
            const float* uc = (n < 64) ? &g_U2[(b * 64 + n) * 4] : &g_U3[(b * 64 + n - 64) * 4];
            float4 u = *(const float4*)uc;
            float d = u1.x * u.x + u1.y * u.y + u1.z * u.z + u1.w * u.w;
            s += d; m = fmaxf(m, d);
        }
#pragma unroll
        for (int o = 16; o; o >>= 1) {
            s += __shfl_xor_sync(0xFFFFFFFFu, s, o);
            m = fmaxf(m, __shfl_xor_sync(0xFFFFFFFFu, m, o));
        }
        if (lane == 0) { g_ga[g] = s * (1.f / 128.f); g_gm[g] = m; }
    } else {
        int g = (bid - 384) * 8 + wid;
        int b = g >> 8, o = g & 255;
        float s0 = 0.f, s1 = 0.f, s2 = 0.f, s3 = 0.f;
#pragma unroll
        for (int it = 0; it < 8; it++) {
            int i = it * 32 + lane;
            float w = Wr[(size_t)o * CC + i];
            float4 u = *(const float4*)&g_U1[(size_t)(b * CC + i) * 4];
            s0 = fmaf(w, u.x, s0); s1 = fmaf(w, u.y, s1);
            s2 = fmaf(w, u.z, s2); s3 = fmaf(w, u.w, s3);
        }
#pragma unroll
        for (int o2 = 16; o2; o2 >>= 1) {
            s0 += __shfl_xor_sync(0xFFFFFFFFu, s0, o2);
            s1 += __shfl_xor_sync(0xFFFFFFFFu, s1, o2);
            s2 += __shfl_xor_sync(0xFFFFFFFFu, s2, o2);
            s3 += __shfl_xor_sync(0xFFFFFFFFu, s3, o2);
        }
        if (lane == 0) {
            float* v = &g_V1[(size_t)g * 4];
            v[0] = lam[0] * s0; v[1] = lam[1] * s1;
            v[2] = lam[2] * s2; v[3] = lam[3] * s3;
        }
    }
}

// ---------------- K4: spectral (warp-parallel) ------------------------------
__global__ __launch_bounds__(256) void spectral_kernel(const float* __restrict__ Wsa,
                                                       const float* __restrict__ bsa,
                                                       const float* __restrict__ Wsm,
                                                       const float* __restrict__ bsm) {
    int g = blockIdx.x * 8 + (threadIdx.x >> 5);
    int lane = threadIdx.x & 31;
    int b = g >> 8, o = g & 255;
    float s = 0.f;
#pragma unroll
    for (int it = 0; it < 8; it++) {
        int i = it * 32 + lane;
        s += Wsa[(size_t)o * CC + i] * g_ga[b * CC + i]
           + Wsm[(size_t)o * CC + i] * g_gm[b * CC + i];
    }
#pragma unroll
    for (int o2 = 16; o2; o2 >>= 1) s += __shfl_xor_sync(0xFFFFFFFFu, s, o2);
    if (lane == 0) {
        s += bsa[o] + bsm[o];
        g_spec[g] = sigm(sigm(s));
    }
}

// ---------------- K5: fused epilogue (both outputs) -------------------------
// NOTE einsum "bcr,bhr,bwr": U2 is indexed by h, U3 by w.
__global__ __launch_bounds__(256) void epilogue_kernel(const float* __restrict__ frm,
                                                       const float* __restrict__ other,
                                                       const float* __restrict__ br,
                                                       const float* __restrict__ alpha_p,
                                                       float* __restrict__ out) {
    int e = blockIdx.x * 256 + threadIdx.x;
    int i4 = e * 4;
    int b = i4 >> 20;
    int c = (i4 >> 12) & 255;
    int h = (i4 >> 6) & 63;
    int w0 = i4 & 63;

    float alpha = alpha_p[0];
    float spec = g_spec[b * CC + c];
    float4 sp4 = *(const float4*)&g_spatial[(b * HH + h) * WW + w0];
    float sp[4] = { sp4.x, sp4.y, sp4.z, sp4.w };
    float4 f4 = *(const float4*)&frm[i4];
    float4 o4 = *(const float4*)&other[i4];
    uint2 mraw = *(const uint2*)&g_Fm[i4];
    float2 mlo = __half22float2(*(__half2*)&mraw.x);
    float2 mhi = __half22float2(*(__half2*)&mraw.y);

    float4 v1 = *(const float4*)&g_V1[(size_t)(b * CC + c) * 4];
    float4 u2h = *(const float4*)&g_U2[(b * 64 + h) * 4];
    float vr0 = v1.x * u2h.x, vr1 = v1.y * u2h.y;
    float vr2 = v1.z * u2h.z, vr3 = v1.w * u2h.w;
    float brc = br[c];

    float fu[4], cr[4];
    float fr[4] = { f4.x, f4.y, f4.z, f4.w };
    float ot[4] = { o4.x, o4.y, o4.z, o4.w };
    float fm[4] = { mlo.x, mlo.y, mhi.x, mhi.y };
#pragma unroll
    for (int j = 0; j < 4; j++) {
        float wt = spec * sp[j];
        fu[j] = alpha * wt * fr[j] + (1.f - alpha) * (1.f - wt) * ot[j];
        float4 u3w = *(const float4*)&g_U3[(b * 64 + w0 + j) * 4];
        float cp = brc + vr0 * u3w.x + vr1 * u3w.y + vr2 * u3w.z + vr3 * u3w.w;
        cr[j] = cp * wt + fm[j];
    }
    *(float4*)&out[i4] = make_float4(fu[0], fu[1], fu[2], fu[3]);
    *(float4*)&out[NOUT + i4] = make_float4(cr[0], cr[1], cr[2], cr[3]);
}

// ---------------- launch -----------------------------------------------------
extern "C" void kernel_launch(void* const* d_in, const int* in_sizes, int n_in,
                              void* d_out, int out_size) {
    const float* frm   = (const float*)d_in[0];
    const float* other = (const float*)d_in[1];
    const float* W3    = (const float*)d_in[2];
    const float* b3    = (const float*)d_in[3];
    const float* Wa1   = (const float*)d_in[4];
    const float* ba1   = (const float*)d_in[5];
    const float* Wa2   = (const float*)d_in[6];
    const float* ba2   = (const float*)d_in[7];
    const float* Wa3   = (const float*)d_in[8];
    const float* ba3   = (const float*)d_in[9];
    const float* Wu    = (const float*)d_in[10];
    const float* bu    = (const float*)d_in[11];
    const float* Wr    = (const float*)d_in[12];
    const float* br    = (const float*)d_in[13];
    const float* ws    = (const float*)d_in[14];
    const float* bs    = (const float*)d_in[15];
    const float* Wsa   = (const float*)d_in[16];
    const float* bsa   = (const float*)d_in[17];
    const float* Wsm   = (const float*)d_in[18];
    const float* bsm   = (const float*)d_in[19];
    const float* alpha = (const float*)d_in[20];
    const float* lam   = (const float*)d_in[21];
    float* out = (float*)d_out;

    prep_kernel<<<PW_BLOCKS + 4096, 256>>>(W3, frm, other, Wu, bu,
                                           Wa1, ba1, Wa2, ba2, Wa3, ba3);

    cudaFuncSetAttribute(conv_mma_kernel, cudaFuncAttributeMaxDynamicSharedMemorySize, DSMEM_BYTES);
    conv_mma_kernel<<<dim3(128, 2), 512, DSMEM_BYTES>>>(b3);

    modes_pass1_kernel<<<2048, 256>>>();
    modes_final_kernel<<<128, 256>>>();
    small_kernel<<<640, 256>>>(Wr, lam, ws, bs);
    spectral_kernel<<<256, 256>>>(Wsa, bsa, Wsm, bsm);
    epilogue_kernel<<<NOUT / 4 / 256, 256>>>(frm, other, br, alpha, out);
}